// round 14
// baseline (speedup 1.0000x reference)
#include <cuda_runtime.h>

#define N_NODES 50000
#define N_EDGES 200000
#define OUTD 32
#define IN_SELF 128
#define EDGE_DIM 16

#define EDGE_BLOCKS 592
#define EDGE_THREADS 256

#define BN 128          // nodes per block == threads per block
#define KB 16           // k-chunk
#define BNP 132         // padded node stride
#define NT 128
#define SB 391

// Zero-initialized at module load; node_kernel restores zeros post-epilogue,
// so the zero-invariant holds across graph replays with no memset launch.
__device__ float g_scratch[N_NODES * OUTD + N_NODES];

__device__ __forceinline__ void red_add_v4(float* ptr, float4 v) {
    asm volatile("red.global.add.v4.f32 [%0], {%1, %2, %3, %4};"
                 :: "l"(ptr), "f"(v.x), "f"(v.y), "f"(v.z), "f"(v.w)
                 : "memory");
}

__device__ __forceinline__ void fma2(unsigned long long& d,
                                     unsigned long long a,
                                     unsigned long long b) {
    asm("fma.rn.f32x2 %0, %1, %2, %0;" : "+l"(d) : "l"(a), "l"(b));
}

__device__ __forceinline__ unsigned long long packdup(float v) {
    unsigned long long r;
    asm("mov.b64 %0, {%1, %1};" : "=l"(r) : "f"(v));
    return r;
}

// ---------------------------------------------------------------------------
// Edge kernel (R10 verbatim, proven): software-pipelined scatter.
// ---------------------------------------------------------------------------
__global__ void __launch_bounds__(EDGE_THREADS)
edge_kernel(const float* __restrict__ h_neigh,
            const float* __restrict__ edge_features,
            const float* __restrict__ W_edge,
            const float* __restrict__ b_edge,
            const int* __restrict__ src,
            const int* __restrict__ dst) {
    __shared__ __align__(16) float sW[EDGE_DIM * OUTD];
    __shared__ __align__(16) float sb[OUTD];
    {
        for (int idx = threadIdx.x; idx < OUTD * EDGE_DIM; idx += EDGE_THREADS) {
            int j = idx >> 4, k = idx & 15;
            float s = 0.f;
            #pragma unroll
            for (int i = 0; i < OUTD; i++)
                s += W_edge[(i * OUTD + j) * EDGE_DIM + k];
            sW[k * OUTD + j] = s;
        }
        if (threadIdx.x < OUTD) {
            float s2 = 0.f;
            #pragma unroll
            for (int i = 0; i < OUTD; i++)
                s2 += b_edge[i * OUTD + threadIdx.x];
            sb[threadIdx.x] = s2;
        }
    }
    __syncthreads();

    float* g_agg = g_scratch;
    float* g_deg = g_scratch + N_NODES * OUTD;

    const int lane = threadIdx.x & 31;
    const int warp = threadIdx.x >> 5;
    const int g = lane >> 3;
    const int p = lane & 7;
    const int wpb = EDGE_THREADS >> 5;
    const int nwarps = EDGE_BLOCKS * wpb;
    const int NGROUPS = N_EDGES / 4;

    const float4 biasv = *reinterpret_cast<const float4*>(&sb[4 * p]);

    int grp = blockIdx.x * wpb + warp;
    if (grp >= NGROUPS) return;

    int s = src[grp * 4 + g];
    int d = dst[grp * 4 + g];
    float2 ef = *reinterpret_cast<const float2*>(
        &edge_features[grp * 4 * EDGE_DIM + lane * 2]);

    #pragma unroll 1
    while (true) {
        float4 hv = *reinterpret_cast<const float4*>(&h_neigh[s * OUTD + 4 * p]);

        int next = grp + nwarps;
        int s2 = 0, d2 = 0;
        float2 ef2 = make_float2(0.f, 0.f);
        bool more = (next < NGROUPS);
        if (more) {
            s2 = src[next * 4 + g];
            d2 = dst[next * 4 + g];
            ef2 = *reinterpret_cast<const float2*>(
                &edge_features[next * 4 * EDGE_DIM + lane * 2]);
        }

        float4 acc = biasv;
        #pragma unroll
        for (int k = 0; k < EDGE_DIM; k++) {
            float ek = __shfl_sync(0xffffffffu, (k & 1) ? ef.y : ef.x, k >> 1, 8);
            float4 w = *reinterpret_cast<const float4*>(&sW[k * OUTD + 4 * p]);
            acc.x = fmaf(ek, w.x, acc.x);
            acc.y = fmaf(ek, w.y, acc.y);
            acc.z = fmaf(ek, w.z, acc.z);
            acc.w = fmaf(ek, w.w, acc.w);
        }

        float4 msg = make_float4(hv.x * acc.x, hv.y * acc.y,
                                 hv.z * acc.z, hv.w * acc.w);
        red_add_v4(&g_agg[d * OUTD + 4 * p], msg);
        if (p == 0) atomicAdd(&g_deg[d], 1.0f);

        if (!more) break;
        s = s2; d = d2; ef = ef2; grp = next;
    }
}

// ---------------------------------------------------------------------------
// Node kernel: thread-per-node broadcast GEMV.
//   Thread t owns node nbase+t and ALL 32 output channels (16 f32x2 accs).
//   Per k: 1 conflict-free LDS.32 (x) + 4 uniform-broadcast LDS.128 (w row)
//          + 16 independent fma2.  Crossbar: 192 B/warp/k (vs 1536 before).
// ---------------------------------------------------------------------------
__global__ void __launch_bounds__(NT, 6)
node_kernel(const float* __restrict__ h_self,
            const float* __restrict__ W_self,
            const float* __restrict__ W_neigh,
            float* __restrict__ out) {
    __shared__ __align__(16) float h_s[2][KB][BNP];
    __shared__ __align__(16) float w_s[2][KB][OUTD];
    __shared__ float sinv[BN];

    float* g_agg = g_scratch;
    float* g_deg = g_scratch + N_NODES * OUTD;

    const int t = threadIdx.x;
    const int nbase = blockIdx.x * BN;
    const int gn_self = nbase + t;          // this thread's node

    // staging indices: idx = t + i*NT (0..511): node = idx>>2, kvec = idx&3
    const int snode = t >> 2;
    const int skvec = t & 3;
    // w staging: c = t>>2 (0..31), kvec = t&3
    const int wchan = t >> 2;
    const int wkvec = t & 3;

    // sinv + deg self-clean
    {
        if (gn_self < N_NODES) {
            float dv = g_deg[gn_self];
            g_deg[gn_self] = 0.f;
            sinv[t] = 1.0f / fmaxf(dv, 1.0f);
        } else {
            sinv[t] = 0.f;
        }
    }

    float4 hreg[4];
    float4 wreg;

    auto load_regs = [&](int kc) {
        #pragma unroll
        for (int i = 0; i < 4; i++) {
            int node = snode + i * (NT >> 2);    // +0,32,64,96
            int gn = nbase + node;
            float4 v = make_float4(0.f, 0.f, 0.f, 0.f);
            if (gn < N_NODES) {
                if (kc < 8) {
                    v = *reinterpret_cast<const float4*>(
                        &h_self[gn * IN_SELF + kc * KB + skvec * 4]);
                } else {
                    v = *reinterpret_cast<const float4*>(
                        &g_agg[gn * OUTD + (kc - 8) * KB + skvec * 4]);
                    float iv = sinv[node];
                    v.x *= iv; v.y *= iv; v.z *= iv; v.w *= iv;
                }
            }
            hreg[i] = v;
        }
        if (kc < 8)
            wreg = *reinterpret_cast<const float4*>(
                &W_self[wchan * IN_SELF + kc * KB + wkvec * 4]);
        else
            wreg = *reinterpret_cast<const float4*>(
                &W_neigh[wchan * OUTD + (kc - 8) * KB + wkvec * 4]);
    };

    auto store_smem = [&](int b) {
        #pragma unroll
        for (int i = 0; i < 4; i++) {
            int node = snode + i * (NT >> 2);
            h_s[b][skvec * 4 + 0][node] = hreg[i].x;
            h_s[b][skvec * 4 + 1][node] = hreg[i].y;
            h_s[b][skvec * 4 + 2][node] = hreg[i].z;
            h_s[b][skvec * 4 + 3][node] = hreg[i].w;
        }
        w_s[b][wkvec * 4 + 0][wchan] = wreg.x;
        w_s[b][wkvec * 4 + 1][wchan] = wreg.y;
        w_s[b][wkvec * 4 + 2][wchan] = wreg.z;
        w_s[b][wkvec * 4 + 3][wchan] = wreg.w;
    };

    // 16 f32x2 accumulators = channels (2i, 2i+1)
    unsigned long long acc2[16];
    #pragma unroll
    for (int i = 0; i < 16; i++) acc2[i] = 0ull;

    load_regs(0);
    __syncthreads();      // sinv visible (needed from kc=8), smem free
    store_smem(0);
    __syncthreads();

    #pragma unroll
    for (int kc = 0; kc < 10; kc++) {
        int b = kc & 1;
        if (kc < 9) load_regs(kc + 1);
        #pragma unroll
        for (int k = 0; k < KB; k++) {
            unsigned long long xd = packdup(h_s[b][k][t]);   // conflict-free LDS.32
            const ulonglong2* wrow =
                reinterpret_cast<const ulonglong2*>(&w_s[b][k][0]);
            ulonglong2 wA = wrow[0];   // uniform-broadcast LDS.128
            ulonglong2 wB = wrow[1];
            ulonglong2 wC = wrow[2];
            ulonglong2 wD = wrow[3];
            fma2(acc2[0],  xd, wA.x);
            fma2(acc2[1],  xd, wA.y);
            fma2(acc2[2],  xd, wB.x);
            fma2(acc2[3],  xd, wB.y);
            fma2(acc2[4],  xd, wC.x);
            fma2(acc2[5],  xd, wC.y);
            fma2(acc2[6],  xd, wD.x);
            fma2(acc2[7],  xd, wD.y);
            ulonglong2 wE = wrow[4];
            ulonglong2 wF = wrow[5];
            ulonglong2 wG = wrow[6];
            ulonglong2 wH = wrow[7];
            fma2(acc2[8],  xd, wE.x);
            fma2(acc2[9],  xd, wE.y);
            fma2(acc2[10], xd, wF.x);
            fma2(acc2[11], xd, wF.y);
            fma2(acc2[12], xd, wG.x);
            fma2(acc2[13], xd, wG.y);
            fma2(acc2[14], xd, wH.x);
            fma2(acc2[15], xd, wH.y);
        }
        if (kc < 9) store_smem(1 - b);
        __syncthreads();
    }

    // epilogue: unpack, relu, 8x STG.128 (this thread's whole output row)
    if (gn_self < N_NODES) {
        #pragma unroll
        for (int q = 0; q < 8; q++) {
            float2 a = *reinterpret_cast<float2*>(&acc2[2 * q]);
            float2 c = *reinterpret_cast<float2*>(&acc2[2 * q + 1]);
            float4 o = make_float4(fmaxf(a.x, 0.f), fmaxf(a.y, 0.f),
                                   fmaxf(c.x, 0.f), fmaxf(c.y, 0.f));
            *reinterpret_cast<float4*>(&out[gn_self * OUTD + q * 4]) = o;
        }
    }

    // bulk self-clean of this block's agg slice (off critical path)
    {
        const int nvalid = min(BN, N_NODES - nbase);
        const int nq = nvalid * (OUTD / 4);
        float4* ap = reinterpret_cast<float4*>(&g_agg[nbase * OUTD]);
        const float4 z = make_float4(0.f, 0.f, 0.f, 0.f);
        for (int i = t; i < nq; i += NT)
            ap[i] = z;
    }
}

extern "C" void kernel_launch(void* const* d_in, const int* in_sizes, int n_in,
                              void* d_out, int out_size) {
    const float* h_neigh       = (const float*)d_in[0];
    const float* h_self        = (const float*)d_in[1];
    const float* edge_features = (const float*)d_in[2];
    const float* W_edge        = (const float*)d_in[3];
    const float* b_edge        = (const float*)d_in[4];
    const float* W_self        = (const float*)d_in[5];
    const float* W_neigh       = (const float*)d_in[6];
    const int*   src           = (const int*)d_in[7];
    const int*   dst           = (const int*)d_in[8];
    float* out = (float*)d_out;

    edge_kernel<<<EDGE_BLOCKS, EDGE_THREADS>>>(h_neigh, edge_features,
                                               W_edge, b_edge, src, dst);
    node_kernel<<<SB, NT>>>(h_self, W_self, W_neigh, out);
}

// round 16
// speedup vs baseline: 1.2608x; 1.2608x over previous
#include <cuda_runtime.h>
#include <cstdint>

#define N_NODES 50000
#define N_EDGES 200000
#define OUTD 32
#define IN_SELF 128
#define EDGE_DIM 16

#define EDGE_BLOCKS 592
#define EDGE_THREADS 256

#define BN 128
#define NT 128
#define SB 391
#define XS_PAD 36   // stride 36: bank(row*36+col) == lane for fragment loads

__device__ float g_scratch[N_NODES * OUTD + N_NODES];

__device__ __forceinline__ void red_add_v4(float* ptr, float4 v) {
    asm volatile("red.global.add.v4.f32 [%0], {%1, %2, %3, %4};"
                 :: "l"(ptr), "f"(v.x), "f"(v.y), "f"(v.z), "f"(v.w)
                 : "memory");
}

__device__ __forceinline__ uint32_t f2tf32(float x) {
    uint32_t r;
    asm("cvt.rna.tf32.f32 %0, %1;" : "=r"(r) : "f"(x));
    return r;
}

__device__ __forceinline__ void mma_tf32(float* c, const uint32_t* a,
                                         const uint32_t* b) {
    asm volatile(
        "mma.sync.aligned.m16n8k8.row.col.f32.tf32.tf32.f32 "
        "{%0,%1,%2,%3}, {%4,%5,%6,%7}, {%8,%9}, {%0,%1,%2,%3};"
        : "+f"(c[0]), "+f"(c[1]), "+f"(c[2]), "+f"(c[3])
        : "r"(a[0]), "r"(a[1]), "r"(a[2]), "r"(a[3]), "r"(b[0]), "r"(b[1]));
}

// ---------------------------------------------------------------------------
// Edge kernel (R10 verbatim, proven): software-pipelined scatter.
// ---------------------------------------------------------------------------
__global__ void __launch_bounds__(EDGE_THREADS)
edge_kernel(const float* __restrict__ h_neigh,
            const float* __restrict__ edge_features,
            const float* __restrict__ W_edge,
            const float* __restrict__ b_edge,
            const int* __restrict__ src,
            const int* __restrict__ dst) {
    __shared__ __align__(16) float sW[EDGE_DIM * OUTD];
    __shared__ __align__(16) float sb[OUTD];
    {
        for (int idx = threadIdx.x; idx < OUTD * EDGE_DIM; idx += EDGE_THREADS) {
            int j = idx >> 4, k = idx & 15;
            float s = 0.f;
            #pragma unroll
            for (int i = 0; i < OUTD; i++)
                s += W_edge[(i * OUTD + j) * EDGE_DIM + k];
            sW[k * OUTD + j] = s;
        }
        if (threadIdx.x < OUTD) {
            float s2 = 0.f;
            #pragma unroll
            for (int i = 0; i < OUTD; i++)
                s2 += b_edge[i * OUTD + threadIdx.x];
            sb[threadIdx.x] = s2;
        }
    }
    __syncthreads();

    float* g_agg = g_scratch;
    float* g_deg = g_scratch + N_NODES * OUTD;

    const int lane = threadIdx.x & 31;
    const int warp = threadIdx.x >> 5;
    const int g = lane >> 3;
    const int p = lane & 7;
    const int wpb = EDGE_THREADS >> 5;
    const int nwarps = EDGE_BLOCKS * wpb;
    const int NGROUPS = N_EDGES / 4;

    const float4 biasv = *reinterpret_cast<const float4*>(&sb[4 * p]);

    int grp = blockIdx.x * wpb + warp;
    if (grp >= NGROUPS) return;

    int s = src[grp * 4 + g];
    int d = dst[grp * 4 + g];
    float2 ef = *reinterpret_cast<const float2*>(
        &edge_features[grp * 4 * EDGE_DIM + lane * 2]);

    #pragma unroll 1
    while (true) {
        float4 hv = *reinterpret_cast<const float4*>(&h_neigh[s * OUTD + 4 * p]);

        int next = grp + nwarps;
        int s2 = 0, d2 = 0;
        float2 ef2 = make_float2(0.f, 0.f);
        bool more = (next < NGROUPS);
        if (more) {
            s2 = src[next * 4 + g];
            d2 = dst[next * 4 + g];
            ef2 = *reinterpret_cast<const float2*>(
                &edge_features[next * 4 * EDGE_DIM + lane * 2]);
        }

        float4 acc = biasv;
        #pragma unroll
        for (int k = 0; k < EDGE_DIM; k++) {
            float ek = __shfl_sync(0xffffffffu, (k & 1) ? ef.y : ef.x, k >> 1, 8);
            float4 w = *reinterpret_cast<const float4*>(&sW[k * OUTD + 4 * p]);
            acc.x = fmaf(ek, w.x, acc.x);
            acc.y = fmaf(ek, w.y, acc.y);
            acc.z = fmaf(ek, w.z, acc.z);
            acc.w = fmaf(ek, w.w, acc.w);
        }

        float4 msg = make_float4(hv.x * acc.x, hv.y * acc.y,
                                 hv.z * acc.z, hv.w * acc.w);
        red_add_v4(&g_agg[d * OUTD + 4 * p], msg);
        if (p == 0) atomicAdd(&g_deg[d], 1.0f);

        if (!more) break;
        s = s2; d = d2; ef = ef2; grp = next;
    }
}

// ---------------------------------------------------------------------------
// Node kernel: 3xTF32 warp-MMA GEMM (mma.sync.m16n8k8, sm_80+ path).
//   out[n,c] = relu( X[n,:] . Wc[c,:] ),  X=[h_self | agg/deg], K=160.
//   Warp w owns nodes [w*32, w*32+32) x all 32 channels:
//   2 m16-frags x 4 n8-frags, fp32 accumulators.
//   D = Ahi*Bhi + Ahi*Blo + Alo*Bhi   (3xTF32 precision splitting)
// ---------------------------------------------------------------------------
__global__ void __launch_bounds__(NT)
node_kernel(const float* __restrict__ h_self,
            const float* __restrict__ W_self,
            const float* __restrict__ W_neigh,
            float* __restrict__ out) {
    __shared__ float xs[BN][XS_PAD];   // X chunk, fp32 (18KB)
    __shared__ float wh[OUTD][XS_PAD]; // W chunk hi (tf32-rounded, as fp32 bits)
    __shared__ float wl[OUTD][XS_PAD]; // W chunk lo residual
    __shared__ float sinv[BN];

    float* g_agg = g_scratch;
    float* g_deg = g_scratch + N_NODES * OUTD;

    const int t = threadIdx.x;
    const int w = t >> 5;
    const int lane = t & 31;
    const int g = lane >> 2;       // groupID
    const int tig = lane & 3;      // thread-in-group
    const int nbase = blockIdx.x * BN;

    // sinv + deg self-clean
    {
        int gn = nbase + t;
        if (gn < N_NODES) {
            float dv = g_deg[gn];
            g_deg[gn] = 0.f;
            sinv[t] = 1.0f / fmaxf(dv, 1.0f);
        } else {
            sinv[t] = 0.f;
        }
    }
    __syncthreads();

    // accumulators: [mfrag][nfrag][4]
    float acc[2][4][4];
    #pragma unroll
    for (int mf = 0; mf < 2; mf++)
        #pragma unroll
        for (int nf = 0; nf < 4; nf++)
            #pragma unroll
            for (int q = 0; q < 4; q++) acc[mf][nf][q] = 0.f;

    #pragma unroll
    for (int kc = 0; kc < 5; kc++) {
        // ---- stage X chunk: 128 nodes x 32 k ----
        #pragma unroll
        for (int i = 0; i < 8; i++) {
            int idx = t + i * NT;          // 0..1023
            int node = idx >> 3;           // 0..127
            int kvec = idx & 7;            // float4 index
            int gn = nbase + node;
            float4 v = make_float4(0.f, 0.f, 0.f, 0.f);
            if (gn < N_NODES) {
                if (kc < 4) {
                    v = *reinterpret_cast<const float4*>(
                        &h_self[gn * IN_SELF + kc * 32 + kvec * 4]);
                } else {
                    v = *reinterpret_cast<const float4*>(
                        &g_agg[gn * OUTD + kvec * 4]);
                    float iv = sinv[node];
                    v.x *= iv; v.y *= iv; v.z *= iv; v.w *= iv;
                }
            }
            xs[node][kvec * 4 + 0] = v.x;
            xs[node][kvec * 4 + 1] = v.y;
            xs[node][kvec * 4 + 2] = v.z;
            xs[node][kvec * 4 + 3] = v.w;
        }
        // ---- stage W chunk: 32 chans x 32 k, pre-split hi/lo ----
        #pragma unroll
        for (int i = 0; i < 8; i++) {
            int idx = t + i * NT;          // 0..1023
            int c = idx >> 5;              // 0..31
            int k = idx & 31;
            float wv = (kc < 4) ? W_self[c * IN_SELF + kc * 32 + k]
                                : W_neigh[c * OUTD + k];
            uint32_t hb = f2tf32(wv);
            float hf = __uint_as_float(hb);
            wh[c][k] = hf;
            wl[c][k] = wv - hf;
        }
        __syncthreads();

        // ---- compute: 4 k8-steps ----
        #pragma unroll
        for (int ks = 0; ks < 4; ks++) {
            int kb = ks * 8;
            // A fragments (hi + lo) for 2 m16 tiles
            uint32_t ahi[2][4], alo[2][4];
            #pragma unroll
            for (int mf = 0; mf < 2; mf++) {
                #pragma unroll
                for (int j = 0; j < 4; j++) {
                    int row = w * 32 + mf * 16 + g + (j & 1) * 8;
                    int col = kb + tig + (j >> 1) * 4;
                    float x = xs[row][col];
                    uint32_t hb = f2tf32(x);
                    ahi[mf][j] = hb;
                    alo[mf][j] = __float_as_uint(x - __uint_as_float(hb));
                }
            }
            // B fragments (hi + lo) for 4 n8 tiles
            uint32_t bhi[4][2], blo[4][2];
            #pragma unroll
            for (int nf = 0; nf < 4; nf++) {
                int ch = nf * 8 + g;
                bhi[nf][0] = __float_as_uint(wh[ch][kb + tig]);
                bhi[nf][1] = __float_as_uint(wh[ch][kb + tig + 4]);
                blo[nf][0] = __float_as_uint(wl[ch][kb + tig]);
                blo[nf][1] = __float_as_uint(wl[ch][kb + tig + 4]);
            }
            #pragma unroll
            for (int mf = 0; mf < 2; mf++)
                #pragma unroll
                for (int nf = 0; nf < 4; nf++) {
                    mma_tf32(acc[mf][nf], ahi[mf], bhi[nf]);
                    mma_tf32(acc[mf][nf], ahi[mf], blo[nf]);
                    mma_tf32(acc[mf][nf], alo[mf], bhi[nf]);
                }
        }
        __syncthreads();
    }

    // ---- epilogue: relu + float2 stores ----
    #pragma unroll
    for (int mf = 0; mf < 2; mf++) {
        #pragma unroll
        for (int nf = 0; nf < 4; nf++) {
            int col = nf * 8 + 2 * tig;
            int n0 = nbase + w * 32 + mf * 16 + g;
            int n1 = n0 + 8;
            if (n0 < N_NODES) {
                float2 o0 = make_float2(fmaxf(acc[mf][nf][0], 0.f),
                                        fmaxf(acc[mf][nf][1], 0.f));
                *reinterpret_cast<float2*>(&out[n0 * OUTD + col]) = o0;
            }
            if (n1 < N_NODES) {
                float2 o1 = make_float2(fmaxf(acc[mf][nf][2], 0.f),
                                        fmaxf(acc[mf][nf][3], 0.f));
                *reinterpret_cast<float2*>(&out[n1 * OUTD + col]) = o1;
            }
        }
    }

    // ---- bulk self-clean of this block's agg slice ----
    {
        const int nvalid = min(BN, N_NODES - nbase);
        const int nq = nvalid * (OUTD / 4);
        float4* ap = reinterpret_cast<float4*>(&g_agg[nbase * OUTD]);
        const float4 z = make_float4(0.f, 0.f, 0.f, 0.f);
        for (int i = t; i < nq; i += NT)
            ap[i] = z;
    }
}

extern "C" void kernel_launch(void* const* d_in, const int* in_sizes, int n_in,
                              void* d_out, int out_size) {
    const float* h_neigh       = (const float*)d_in[0];
    const float* h_self        = (const float*)d_in[1];
    const float* edge_features = (const float*)d_in[2];
    const float* W_edge        = (const float*)d_in[3];
    const float* b_edge        = (const float*)d_in[4];
    const float* W_self        = (const float*)d_in[5];
    const float* W_neigh       = (const float*)d_in[6];
    const int*   src           = (const int*)d_in[7];
    const int*   dst           = (const int*)d_in[8];
    float* out = (float*)d_out;

    // Two launches, no memset: scratch zeroed at load; node_kernel restores
    // zeros (deg in sinv setup, agg post-epilogue) -> replay-safe.
    edge_kernel<<<EDGE_BLOCKS, EDGE_THREADS>>>(h_neigh, edge_features,
                                               W_edge, b_edge, src, dst);
    node_kernel<<<SB, NT>>>(h_self, W_self, W_neigh, out);
}